// round 4
// baseline (speedup 1.0000x reference)
#include <cuda_runtime.h>
#include <math.h>
#include <stdint.h>

#define BB 4
#define SS 2048
#define HH 1024
#define INNERD 512
#define RAD 8
#define KSTEPS 4
#define LAMv 0.1f
#define MU_MAXV 10.0f

#define BSH (BB*SS*HH)

// Scratch (no cudaMalloc allowed). Ping-pong state buffers.
__device__ float g_q[BSH];
__device__ float g_stateA[BSH];
__device__ float g_stateB[BSH];
__device__ float g_nsq[BB*SS];
__device__ float g_dots[BB*RAD*SS];
__device__ float g_mu[BB*RAD*SS];
__device__ float g_isq[BB*SS];

__device__ __forceinline__ void cp_async16(uint32_t s, const void* g) {
    asm volatile("cp.async.ca.shared.global [%0], [%1], 16;" :: "r"(s), "l"(g));
}
__device__ __forceinline__ void cp_commit() {
    asm volatile("cp.async.commit_group;");
}
template<int N>
__device__ __forceinline__ void cp_wait() {
    asm volatile("cp.async.wait_group %0;" :: "n"(N));
}

// ---------------------------------------------------------------------------
// GEMM (TF32 mma.sync, cp.async double-buffered): q = hidden @ Wq + bq.
// Block 128x128, 8 warps (warp 32x64), K-step 32, 2 stages.
// ---------------------------------------------------------------------------
#define TM 128
#define TN 128
#define TK 32
#define AS_LD (TK + 4)    // As[m][k] row length (36)
#define BS_LD (TN + 4)    // Bs[k][n] row length (132)
#define AS_STAGE (TM * AS_LD)
#define BS_STAGE (TK * BS_LD)
#define GEMM_SMEM ((2*AS_STAGE + 2*BS_STAGE) * sizeof(float))

__global__ __launch_bounds__(256) void gemm_tf32_kernel(
    const float* __restrict__ A,
    const float* __restrict__ W,
    const float* __restrict__ bias)
{
    extern __shared__ float sm[];
    float* As = sm;                       // 2 stages, [m][k]
    float* Bs = sm + 2 * AS_STAGE;        // 2 stages, [k][n]
    uint32_t as_u = (uint32_t)__cvta_generic_to_shared(As);
    uint32_t bs_u = (uint32_t)__cvta_generic_to_shared(Bs);

    const int N = HH, K = HH;
    int tid = threadIdx.x;
    int m0 = blockIdx.y * TM;
    int n0 = blockIdx.x * TN;
    int wid = tid >> 5, lane = tid & 31;
    int wm = (wid & 3) * 32;
    int wn = (wid >> 2) * 64;
    int gid = lane >> 2, tig = lane & 3;

    float acc[2][8][4];
#pragma unroll
    for (int mt = 0; mt < 2; mt++)
#pragma unroll
        for (int nt = 0; nt < 8; nt++)
#pragma unroll
            for (int c = 0; c < 4; c++) acc[mt][nt][c] = 0.f;

    // loader mapping: A tile = 1024 float4 (8 per row), B tile = 1024 float4
    int am[4], ak[4], bk[4], bn[4];
#pragma unroll
    for (int r = 0; r < 4; r++) {
        int f = tid + 256 * r;
        am[r] = f >> 3;  ak[r] = (f & 7) * 4;
        bk[r] = f >> 5;  bn[r] = (f & 31) * 4;
    }

#define LOAD_STAGE(s, k0)                                                     \
    {                                                                         \
        _Pragma("unroll")                                                     \
        for (int r = 0; r < 4; r++) {                                         \
            cp_async16(as_u + (((s)*TM + am[r]) * AS_LD + ak[r]) * 4,         \
                       &A[(size_t)(m0 + am[r]) * K + (k0) + ak[r]]);          \
            cp_async16(bs_u + (((s)*TK + bk[r]) * BS_LD + bn[r]) * 4,         \
                       &W[(size_t)((k0) + bk[r]) * N + n0 + bn[r]]);          \
        }                                                                     \
        cp_commit();                                                          \
    }

    LOAD_STAGE(0, 0);

    const int NIT = K / TK;   // 32
    for (int it = 0; it < NIT; it++) {
        if (it + 1 < NIT) {
            LOAD_STAGE((it + 1) & 1, (it + 1) * TK);
            cp_wait<1>();
        } else {
            cp_wait<0>();
        }
        __syncthreads();

        int buf = it & 1;
        const float* Ab = As + buf * AS_STAGE;
        const float* Bb = Bs + buf * BS_STAGE;
#pragma unroll
        for (int ks = 0; ks < 4; ks++) {
            int kb = ks * 8;
            uint32_t af[2][4];
#pragma unroll
            for (int mt = 0; mt < 2; mt++) {
                int rm = wm + mt * 16 + gid;
                af[mt][0] = __float_as_uint(Ab[rm * AS_LD + kb + tig]);
                af[mt][1] = __float_as_uint(Ab[(rm + 8) * AS_LD + kb + tig]);
                af[mt][2] = __float_as_uint(Ab[rm * AS_LD + kb + tig + 4]);
                af[mt][3] = __float_as_uint(Ab[(rm + 8) * AS_LD + kb + tig + 4]);
            }
            uint32_t bf[8][2];
#pragma unroll
            for (int nt = 0; nt < 8; nt++) {
                int cn = wn + nt * 8 + gid;
                bf[nt][0] = __float_as_uint(Bb[(kb + tig) * BS_LD + cn]);
                bf[nt][1] = __float_as_uint(Bb[(kb + tig + 4) * BS_LD + cn]);
            }
#pragma unroll
            for (int mt = 0; mt < 2; mt++)
#pragma unroll
                for (int nt = 0; nt < 8; nt++) {
                    asm volatile(
                        "mma.sync.aligned.m16n8k8.row.col.f32.tf32.tf32.f32 "
                        "{%0,%1,%2,%3}, {%4,%5,%6,%7}, {%8,%9}, {%0,%1,%2,%3};"
                        : "+f"(acc[mt][nt][0]), "+f"(acc[mt][nt][1]),
                          "+f"(acc[mt][nt][2]), "+f"(acc[mt][nt][3])
                        : "r"(af[mt][0]), "r"(af[mt][1]),
                          "r"(af[mt][2]), "r"(af[mt][3]),
                          "r"(bf[nt][0]), "r"(bf[nt][1]));
                }
        }
        __syncthreads();
    }

#pragma unroll
    for (int mt = 0; mt < 2; mt++) {
        int row0 = m0 + wm + mt * 16 + gid;
#pragma unroll
        for (int nt = 0; nt < 8; nt++) {
            int col = n0 + wn + nt * 8 + 2 * tig;
            float bx = bias[col], by = bias[col + 1];
            float2 v0 = make_float2(acc[mt][nt][0] + bx, acc[mt][nt][1] + by);
            float2 v1 = make_float2(acc[mt][nt][2] + bx, acc[mt][nt][3] + by);
            *(float2*)&g_q[(size_t)row0 * N + col] = v0;
            *(float2*)&g_q[(size_t)(row0 + 8) * N + col] = v1;
        }
    }
}

// ---------------------------------------------------------------------------
// Tiled dots: 512 threads, warp-per-node, DT=16 nodes (+8 halo).
// nsq[i] = ||s_i||^2 ; dots[d][i] = <s_i, s_{i+d}>.
// ---------------------------------------------------------------------------
#define DT 16
#define DROWS 24
#define DOTS_SMEM (DROWS * HH * sizeof(float))

__global__ __launch_bounds__(512) void dots_tiled_kernel(const float* __restrict__ src)
{
    extern __shared__ float sh[];  // DROWS * HH
    int tid = threadIdx.x;
    int b = blockIdx.y;
    int i0 = blockIdx.x * DT;

#pragma unroll
    for (int r = 0; r < 12; r++) {
        int slot = tid + 512 * r;            // over DROWS*256 float4
        int row = slot >> 8;
        int c4 = slot & 255;
        int i = i0 + row;
        if (i < SS)
            ((float4*)(sh + (size_t)row * HH))[c4] =
                ((const float4*)(src + ((size_t)b * SS + i) * HH))[c4];
    }
    __syncthreads();

    int w = tid >> 5, lane = tid & 31;
    int i = i0 + w;
    if (i >= SS) return;
    const float4* arow = (const float4*)(sh + (size_t)w * HH);
    float4 a[8];
#pragma unroll
    for (int r = 0; r < 8; r++) a[r] = arow[lane + 32 * r];

#pragma unroll
    for (int d = 0; d <= RAD; d++) {
        if (d > 0 && i + d >= SS) break;
        float sum = 0.f;
        if (d == 0) {
#pragma unroll
            for (int r = 0; r < 8; r++)
                sum += a[r].x*a[r].x + a[r].y*a[r].y + a[r].z*a[r].z + a[r].w*a[r].w;
        } else {
            const float4* crow = (const float4*)(sh + (size_t)(w + d) * HH);
#pragma unroll
            for (int r = 0; r < 8; r++) {
                float4 c = crow[lane + 32 * r];
                sum += a[r].x*c.x + a[r].y*c.y + a[r].z*c.z + a[r].w*c.w;
            }
        }
#pragma unroll
        for (int o = 16; o > 0; o >>= 1)
            sum += __shfl_xor_sync(0xffffffffu, sum, o);
        if (lane == 0) {
            if (d == 0) g_nsq[b * SS + i] = sum;
            else g_dots[((size_t)b * RAD + (d - 1)) * SS + i] = sum;
        }
    }
}

// ---------------------------------------------------------------------------
// mu: 8 threads per edge (64 channels each), weights in smem, GELU fast-path.
// ---------------------------------------------------------------------------
__global__ __launch_bounds__(256) void mu_kernel3(
    const float* __restrict__ W1, const float* __restrict__ b1,
    const float* __restrict__ W2, const float* __restrict__ b2)
{
    __shared__ float w1a[INNERD], w1b[INNERD], bb1[INNERD], w2s[INNERD];
    int tid = threadIdx.x;
#pragma unroll
    for (int r = 0; r < 2; r++) {
        int k = tid + 256 * r;
        w1a[k] = W1[k];
        w1b[k] = W1[INNERD + k];
        bb1[k] = b1[k];
        w2s[k] = W2[k];
    }
    __syncthreads();

    int e = blockIdx.x * 32 + (tid >> 3);     // edge id
    int sub = tid & 7;
    int b = e >> 14;
    int r = e & 16383;
    int d = (r >> 11) + 1;
    int i = r & 2047;
    size_t slot = ((size_t)b * RAD + (d - 1)) * SS + i;
    bool valid = (i + d < SS);

    int j = valid ? (i + d) : i;
    float nsqi = g_nsq[b * SS + i];
    float nsqj = g_nsq[b * SS + j];
    float dot  = valid ? g_dots[slot] : 0.f;
    float dist = sqrtf(fmaxf(nsqi + nsqj - 2.f * dot, 0.f));
    float ni = fmaxf(sqrtf(nsqi), 1e-6f);
    float nj = fmaxf(sqrtf(nsqj), 1e-6f);
    float cosv = dot / (ni * nj);

    float z = 0.f;
    int kbase = sub * 64;
#pragma unroll 4
    for (int k = kbase; k < kbase + 64; k += 4) {
        float4 wa = *(const float4*)&w1a[k];
        float4 wb = *(const float4*)&w1b[k];
        float4 bv = *(const float4*)&bb1[k];
        float4 w2v = *(const float4*)&w2s[k];
        float x0 = fmaf(dist, wa.x, fmaf(cosv, wb.x, bv.x));
        float x1 = fmaf(dist, wa.y, fmaf(cosv, wb.y, bv.y));
        float x2 = fmaf(dist, wa.z, fmaf(cosv, wb.z, bv.z));
        float x3 = fmaf(dist, wa.w, fmaf(cosv, wb.w, bv.w));
        float g0 = fmaxf(x0, 0.f);
        float g1 = fmaxf(x1, 0.f);
        float g2 = fmaxf(x2, 0.f);
        float g3 = fmaxf(x3, 0.f);
        if (fabsf(x0) < 6.f) g0 = 0.5f*x0*(1.f + erff(x0 * 0.70710678118654752f));
        if (fabsf(x1) < 6.f) g1 = 0.5f*x1*(1.f + erff(x1 * 0.70710678118654752f));
        if (fabsf(x2) < 6.f) g2 = 0.5f*x2*(1.f + erff(x2 * 0.70710678118654752f));
        if (fabsf(x3) < 6.f) g3 = 0.5f*x3*(1.f + erff(x3 * 0.70710678118654752f));
        z = fmaf(g0, w2v.x, z);
        z = fmaf(g1, w2v.y, z);
        z = fmaf(g2, w2v.z, z);
        z = fmaf(g3, w2v.w, z);
    }
    z += __shfl_xor_sync(0xffffffffu, z, 1);
    z += __shfl_xor_sync(0xffffffffu, z, 2);
    z += __shfl_xor_sync(0xffffffffu, z, 4);
    if (sub == 0) {
        if (!valid) { g_mu[slot] = 0.f; return; }
        float zz = z + b2[0];
        float sp = fmaxf(zz, 0.f) + log1pf(expf(-fabsf(zz)));
        g_mu[slot] = fminf(sp + 1e-5f, MU_MAXV);
    }
}

// ---------------------------------------------------------------------------
// deg -> isq
// ---------------------------------------------------------------------------
__global__ void deg_kernel()
{
    int i = blockIdx.x * blockDim.x + threadIdx.x;
    int b = blockIdx.y;
    if (i >= SS) return;
    float deg = 0.f;
#pragma unroll
    for (int d = 1; d <= RAD; d++) {
        if (i + d < SS) deg += g_mu[((size_t)b * RAD + (d - 1)) * SS + i];
        if (i >= d)     deg += g_mu[((size_t)b * RAD + (d - 1)) * SS + i - d];
    }
    g_isq[b * SS + i] = 1.f / sqrtf(fmaxf(deg, 1e-6f));
}

// ---------------------------------------------------------------------------
// Fused lap+update+smooth. src -> dst (ping-pong, race-free).
// LT=32 output rows, 50 state rows in smem, tmp rows in rolling registers.
// 512 threads, each owns 2 columns (float2).
// ---------------------------------------------------------------------------
#define LT 32
#define LSROWS (LT + 18)     // 50
#define LTROWS (LT + 2)      // 34
#define LAPS_SMEM ((LSROWS * HH + LTROWS * 16 + LTROWS) * sizeof(float))

__global__ __launch_bounds__(512) void lapsmooth_kernel(
    const float* __restrict__ src, float* __restrict__ dst, float eta)
{
    extern __shared__ float sh[];
    float* st  = sh;                         // LSROWS * HH
    float* cof = st + (size_t)LSROWS * HH;   // LTROWS * 16
    float* csm = cof + LTROWS * 16;          // LTROWS

    int tid = threadIdx.x;
    int b = blockIdx.y;
    int i0 = blockIdx.x * LT;
    int c2 = tid * 2;                        // column pair

    // load state rows [i0-9, i0+41)
#pragma unroll
    for (int r = 0; r < LSROWS; r++) {
        int j = i0 - 9 + r;
        if (j >= 0 && j < SS)
            *(float2*)&st[(size_t)r * HH + c2] =
                *(const float2*)&src[((size_t)b * SS + j) * HH + c2];
    }
    // coefficients for LTROWS tmp rows (clamped je)
    for (int idx = tid; idx < LTROWS * 16; idx += 512) {
        int jl = idx >> 4;
        int k = idx & 15;
        int j = i0 - 1 + jl;
        int je = min(max(j, 0), SS - 1);
        int d = (k >> 1) + 1;
        float c = 0.f;
        if (!(k & 1)) {
            int jn = je + d;
            if (jn < SS)
                c = g_mu[((size_t)b * RAD + (d - 1)) * SS + je] *
                    g_isq[b * SS + je] * g_isq[b * SS + jn];
        } else {
            int jn = je - d;
            if (jn >= 0)
                c = g_mu[((size_t)b * RAD + (d - 1)) * SS + jn] *
                    g_isq[b * SS + je] * g_isq[b * SS + jn];
        }
        cof[idx] = c;
    }
    __syncthreads();
    if (tid < LTROWS) {
        float s = 0.f;
#pragma unroll
        for (int k = 0; k < 16; k++) s += cof[tid * 16 + k];
        csm[tid] = s;
    }
    __syncthreads();

    float2 t0, t1, t2;
#pragma unroll
    for (int jl = 0; jl < LTROWS; jl++) {
        int j = i0 - 1 + jl;
        int je = min(max(j, 0), SS - 1);
        int jloc = je - i0 + 9;
        float2 si = *(const float2*)&st[(size_t)jloc * HH + c2];
        float cs = csm[jl];
        float2 acc;
        acc.x = cs * si.x; acc.y = cs * si.y;
#pragma unroll
        for (int k = 0; k < 16; k++) {
            float c = cof[jl * 16 + k];
            if (c != 0.f) {
                int d = (k >> 1) + 1;
                int off = (k & 1) ? -d : d;
                float2 sj = *(const float2*)&st[(size_t)(jloc + off) * HH + c2];
                acc.x = fmaf(-c, sj.x, acc.x);
                acc.y = fmaf(-c, sj.y, acc.y);
            }
        }
        float2 qv = *(const float2*)&g_q[((size_t)b * SS + je) * HH + c2];
        float2 tv;
        tv.x = si.x - eta * (acc.x - qv.x);
        tv.y = si.y - eta * (acc.y - qv.y);
        t0 = t1; t1 = t2; t2 = tv;
        if (jl >= 2) {
            int i = i0 + jl - 2;
            float2 o;
            o.x = t1.x - LAMv * (2.f * t1.x - t0.x - t2.x);
            o.y = t1.y - LAMv * (2.f * t1.y - t0.y - t2.y);
            *(float2*)&dst[((size_t)b * SS + i) * HH + c2] = o;
        }
    }
}

// ---------------------------------------------------------------------------
// energy[b] = 0.5 * sum_e mu_e * (nsq_i + nsq_j - 2 dot_e)
// ---------------------------------------------------------------------------
__global__ __launch_bounds__(256) void energy_kernel(float* __restrict__ out)
{
    int b = blockIdx.x;
    int tid = threadIdx.x;
    float partial = 0.f;
    for (int e = tid; e < RAD * SS; e += 256) {
        int d = e >> 11;
        int i = e & 2047;
        if (i + d + 1 < SS) {
            size_t slot = ((size_t)b * RAD + d) * SS + i;
            float mu = g_mu[slot];
            float dsq = g_nsq[b * SS + i] + g_nsq[b * SS + i + d + 1]
                      - 2.f * g_dots[slot];
            partial += mu * dsq;
        }
    }
#pragma unroll
    for (int o = 16; o > 0; o >>= 1)
        partial += __shfl_xor_sync(0xffffffffu, partial, o);
    __shared__ float red[8];
    int wid = tid >> 5, lane = tid & 31;
    if (lane == 0) red[wid] = partial;
    __syncthreads();
    if (tid == 0) {
        float s = 0.f;
#pragma unroll
        for (int w = 0; w < 8; w++) s += red[w];
        out[(size_t)BSH + b] = 0.5f * s;
    }
}

// ---------------------------------------------------------------------------
// out = layernorm(final + hidden) * gamma + beta
// ---------------------------------------------------------------------------
__global__ __launch_bounds__(256) void ln_kernel(
    const float* __restrict__ fin,
    const float* __restrict__ hidden,
    const float* __restrict__ gamma, const float* __restrict__ beta,
    float* __restrict__ out)
{
    int i = blockIdx.x, b = blockIdx.y;
    int tid = threadIdx.x;
    size_t base = ((size_t)b * SS + i) * HH + tid * 4;
    float4 s = *(const float4*)&fin[base];
    float4 h = *(const float4*)&hidden[base];
    float4 x;
    x.x = s.x + h.x; x.y = s.y + h.y; x.z = s.z + h.z; x.w = s.w + h.w;
    float sum = x.x + x.y + x.z + x.w;
    float sq  = x.x*x.x + x.y*x.y + x.z*x.z + x.w*x.w;
#pragma unroll
    for (int o = 16; o > 0; o >>= 1) {
        sum += __shfl_xor_sync(0xffffffffu, sum, o);
        sq  += __shfl_xor_sync(0xffffffffu, sq,  o);
    }
    __shared__ float rs[8], rq[8];
    int wid = tid >> 5, lane = tid & 31;
    if (lane == 0) { rs[wid] = sum; rq[wid] = sq; }
    __syncthreads();
    __shared__ float s_mean, s_rstd;
    if (tid == 0) {
        float ts = 0.f, tq = 0.f;
#pragma unroll
        for (int w = 0; w < 8; w++) { ts += rs[w]; tq += rq[w]; }
        float mean = ts / HH;
        float var = tq / HH - mean * mean;
        s_mean = mean;
        s_rstd = rsqrtf(var + 1e-5f);
    }
    __syncthreads();
    float mean = s_mean, rstd = s_rstd;
    int hbase = tid * 4;
    float4 o;
    o.x = (x.x - mean) * rstd * gamma[hbase+0] + beta[hbase+0];
    o.y = (x.y - mean) * rstd * gamma[hbase+1] + beta[hbase+1];
    o.z = (x.z - mean) * rstd * gamma[hbase+2] + beta[hbase+2];
    o.w = (x.w - mean) * rstd * gamma[hbase+3] + beta[hbase+3];
    *(float4*)&out[base] = o;
}

// ---------------------------------------------------------------------------
extern "C" void kernel_launch(void* const* d_in, const int* in_sizes, int n_in,
                              void* d_out, int out_size)
{
    const float* hidden = (const float*)d_in[0];
    const float* Wq = (const float*)d_in[3];
    const float* bq = (const float*)d_in[4];
    const float* W1 = (const float*)d_in[5];
    const float* b1 = (const float*)d_in[6];
    const float* W2 = (const float*)d_in[7];
    const float* b2 = (const float*)d_in[8];
    const float* gamma = (const float*)d_in[9];
    const float* beta  = (const float*)d_in[10];
    float* out = (float*)d_out;

    float *pA = nullptr, *pB = nullptr;
    cudaGetSymbolAddress((void**)&pA, g_stateA);
    cudaGetSymbolAddress((void**)&pB, g_stateB);

    cudaFuncSetAttribute(gemm_tf32_kernel,
                         cudaFuncAttributeMaxDynamicSharedMemorySize, GEMM_SMEM);
    cudaFuncSetAttribute(dots_tiled_kernel,
                         cudaFuncAttributeMaxDynamicSharedMemorySize, DOTS_SMEM);
    cudaFuncSetAttribute(lapsmooth_kernel,
                         cudaFuncAttributeMaxDynamicSharedMemorySize, LAPS_SMEM);

    gemm_tf32_kernel<<<dim3(HH / TN, (BB * SS) / TM), 256, GEMM_SMEM>>>(hidden, Wq, bq);

    // ping-pong: hidden -> A -> B -> A -> B
    const float* srcs[KSTEPS + 1] = { hidden, pA, pB, pA, pB };
    float*       dsts[KSTEPS]     = { pA, pB, pA, pB };

    const int dots_grid = SS / DT;     // 128
    float eta = 0.1f;
    for (int step = 0; step < KSTEPS; step++) {
        dots_tiled_kernel<<<dim3(dots_grid, BB), 512, DOTS_SMEM>>>(srcs[step]);
        mu_kernel3<<<(BB * RAD * SS) / 32, 256>>>(W1, b1, W2, b2);
        deg_kernel<<<dim3(SS / 256, BB), 256>>>();
        lapsmooth_kernel<<<dim3(SS / LT, BB), 512, LAPS_SMEM>>>(srcs[step], dsts[step], eta);
        eta *= 0.9f;
    }
    dots_tiled_kernel<<<dim3(dots_grid, BB), 512, DOTS_SMEM>>>(srcs[KSTEPS]);
    energy_kernel<<<BB, 256>>>(out);
    ln_kernel<<<dim3(SS, BB), 256>>>(srcs[KSTEPS], hidden, gamma, beta, out);
}